// round 2
// baseline (speedup 1.0000x reference)
#include <cuda_runtime.h>
#include <math.h>
#include <string.h>

#define N_ROWS 131072
#define HID 512
#define RED 128
#define OUTD 512
#define EPS_N 1e-3f
#define LN_EPS 1e-5f

// scratch (allocation-free: static device arrays)
__device__ float g_v2[(size_t)N_ROWS * 512];
__device__ float g_h[(size_t)N_ROWS * 512];

#define FFMA2(d, a, b) asm("fma.rn.f32x2 %0, %1, %2, %0;" : "+l"(d) : "l"(a), "l"(b))

// ---------------- Kernel 1: GEMM1 + scalarizer epilogue ----------------
// Block: 256 threads, 32 v-rows = 96 A-rows. C tile [96][128], K chunk 32.
// f32x2 packed FMA: thread computes 6 rows x 4 column-pairs.

__global__ void __launch_bounds__(256) k1_kernel(const float* __restrict__ v,
                                                 const float* __restrict__ Wd,
                                                 const float* __restrict__ We) {
    __shared__ union {
        struct { float A2[96 * 64]; float B[32 * 130]; } ld;  // A duplicated pairs
        float vred[96 * 128];
    } sm;

    const int tid = threadIdx.x;
    const int tx = tid & 15, ty = tid >> 4;
    const int blk = blockIdx.x;
    const float* Ablk = v + (size_t)blk * 96 * HID;

    unsigned long long acc[6][4];
#pragma unroll
    for (int u = 0; u < 6; u++)
#pragma unroll
        for (int c = 0; c < 4; c++) acc[u][c] = 0ull;

    for (int k0 = 0; k0 < HID; k0 += 32) {
        __syncthreads();
        // A chunk: 96 rows x 32 k (768 float4, 3/thread), duplicated store
#pragma unroll
        for (int t = 0; t < 3; t++) {
            int lin = tid + 256 * t;
            int m = lin >> 3, kq = lin & 7;
            float4 val = *reinterpret_cast<const float4*>(Ablk + (size_t)m * HID + k0 + kq * 4);
            float4* dst = reinterpret_cast<float4*>(sm.ld.A2 + m * 64 + kq * 8);
            dst[0] = make_float4(val.x, val.x, val.y, val.y);
            dst[1] = make_float4(val.z, val.z, val.w, val.w);
        }
        // B chunk transposed: sB[kk][j] = Wd[j][k0+kk], stride 130 (even)
#pragma unroll
        for (int t = 0; t < 4; t++) {
            int lin = tid + 256 * t;
            int j = lin >> 3, kq = lin & 7;
            float4 val = *reinterpret_cast<const float4*>(Wd + (size_t)j * HID + k0 + kq * 4);
            sm.ld.B[(kq * 4 + 0) * 130 + j] = val.x;
            sm.ld.B[(kq * 4 + 1) * 130 + j] = val.y;
            sm.ld.B[(kq * 4 + 2) * 130 + j] = val.z;
            sm.ld.B[(kq * 4 + 3) * 130 + j] = val.w;
        }
        __syncthreads();
#pragma unroll
        for (int kk = 0; kk < 32; kk++) {
            unsigned long long a2[6], b2[4];
#pragma unroll
            for (int u = 0; u < 6; u++)
                a2[u] = *reinterpret_cast<const unsigned long long*>(sm.ld.A2 + (ty + 16 * u) * 64 + 2 * kk);
#pragma unroll
            for (int c = 0; c < 4; c++)
                b2[c] = *reinterpret_cast<const unsigned long long*>(sm.ld.B + kk * 130 + tx * 2 + 32 * c);
#pragma unroll
            for (int u = 0; u < 6; u++)
#pragma unroll
                for (int c = 0; c < 4; c++)
                    FFMA2(acc[u][c], a2[u], b2[c]);
        }
    }
    __syncthreads();
    // dump C tile to smem (vred view), pairs at cols tx*2 + 32c
#pragma unroll
    for (int u = 0; u < 6; u++)
#pragma unroll
        for (int c = 0; c < 4; c++) {
            float2 f;
            memcpy(&f, &acc[u][c], 8);
            *reinterpret_cast<float2*>(&sm.vred[(ty + 16 * u) * 128 + tx * 2 + 32 * c]) = f;
        }
    __syncthreads();

    // ---- epilogue: norms, directions, projections -> v2 ----
    const int warp = tid >> 5, lane = tid & 31;
    float we[3][4];
#pragma unroll
    for (int e = 0; e < 3; e++)
#pragma unroll
        for (int c = 0; c < 4; c++)
            we[e][c] = We[e * RED + lane + 32 * c];

    for (int t = 0; t < 4; t++) {
        int r = warp + 8 * t;  // row within block (0..31)
        size_t grow = (size_t)blk * 32 + r;
        float vr[3][4];
#pragma unroll
        for (int i = 0; i < 3; i++)
#pragma unroll
            for (int c = 0; c < 4; c++)
                vr[i][c] = sm.vred[(r * 3 + i) * 128 + lane + 32 * c];

        float d[3][3];
#pragma unroll
        for (int i = 0; i < 3; i++)
#pragma unroll
            for (int e = 0; e < 3; e++) {
                float s = 0.f;
#pragma unroll
                for (int c = 0; c < 4; c++) s = fmaf(vr[i][c], we[e][c], s);
#pragma unroll
                for (int o = 16; o > 0; o >>= 1)
                    s += __shfl_xor_sync(0xffffffffu, s, o);
                d[i][e] = s;
            }
        float nd[3][3];
#pragma unroll
        for (int e = 0; e < 3; e++) {
            float dn = sqrtf(d[0][e] * d[0][e] + d[1][e] * d[1][e] + d[2][e] * d[2][e]);
            float inv = 1.f / (dn + EPS_N);
            nd[0][e] = d[0][e] * inv;
            nd[1][e] = d[1][e] * inv;
            nd[2][e] = d[2][e] * inv;
        }
        float* v2row = g_v2 + grow * 512;
#pragma unroll
        for (int c = 0; c < 4; c++) {
            float n = sqrtf(vr[0][c] * vr[0][c] + vr[1][c] * vr[1][c] + vr[2][c] * vr[2][c]);
            float invn = 1.f / (n + EPS_N);
            int k = lane + 32 * c;
            v2row[k] = n;
#pragma unroll
            for (int e = 0; e < 3; e++) {
                float p = vr[0][c] * nd[0][e] + vr[1][c] * nd[1][e] + vr[2][c] * nd[2][e];
                v2row[128 + e * 128 + k] = p * invn;
            }
        }
    }
}

// ---------------- Kernel 2: H = v2 @ W_lin^T + b ----------------
// 128x128 C tile, K chunk 32, f32x2: 8 rows x 4 column-pairs per thread.

__global__ void __launch_bounds__(256) k2_kernel(const float* __restrict__ Wl,
                                                 const float* __restrict__ bias) {
    __shared__ float sA2[128 * 64];  // duplicated pairs: 32KB
    __shared__ float sB[32 * 128];   // 16KB -> total exactly 48KB

    const int tid = threadIdx.x;
    const int tx = tid & 15, ty = tid >> 4;
    const size_t row0 = (size_t)blockIdx.x * 128;
    const int col0 = blockIdx.y * 128;

    unsigned long long acc[8][4];
#pragma unroll
    for (int u = 0; u < 8; u++)
#pragma unroll
        for (int c = 0; c < 4; c++) acc[u][c] = 0ull;

    for (int k0 = 0; k0 < 512; k0 += 32) {
        __syncthreads();
        // A chunk: 128 rows x 32 k (4 float4/thread), duplicated store
#pragma unroll
        for (int t = 0; t < 4; t++) {
            int lin = tid + 256 * t;
            int m = lin >> 3, kq = lin & 7;
            float4 val = *reinterpret_cast<const float4*>(g_v2 + (row0 + m) * 512 + k0 + kq * 4);
            float4* dst = reinterpret_cast<float4*>(sA2 + m * 64 + kq * 8);
            dst[0] = make_float4(val.x, val.x, val.y, val.y);
            dst[1] = make_float4(val.z, val.z, val.w, val.w);
        }
        // B chunk transposed: sB[kk][o] = Wl[col0+o][k0+kk], stride 128
#pragma unroll
        for (int t = 0; t < 4; t++) {
            int lin = tid + 256 * t;
            int o = lin >> 3, kq = lin & 7;
            float4 val = *reinterpret_cast<const float4*>(Wl + (size_t)(col0 + o) * 512 + k0 + kq * 4);
            sB[(kq * 4 + 0) * 128 + o] = val.x;
            sB[(kq * 4 + 1) * 128 + o] = val.y;
            sB[(kq * 4 + 2) * 128 + o] = val.z;
            sB[(kq * 4 + 3) * 128 + o] = val.w;
        }
        __syncthreads();
#pragma unroll
        for (int kk = 0; kk < 32; kk++) {
            unsigned long long a2[8], b2[4];
#pragma unroll
            for (int u = 0; u < 8; u++)
                a2[u] = *reinterpret_cast<const unsigned long long*>(sA2 + (ty + 16 * u) * 64 + 2 * kk);
#pragma unroll
            for (int c = 0; c < 4; c++)
                b2[c] = *reinterpret_cast<const unsigned long long*>(sB + kk * 128 + tx * 2 + 32 * c);
#pragma unroll
            for (int u = 0; u < 8; u++)
#pragma unroll
                for (int c = 0; c < 4; c++)
                    FFMA2(acc[u][c], a2[u], b2[c]);
        }
    }
#pragma unroll
    for (int u = 0; u < 8; u++) {
        size_t row = row0 + ty + 16 * u;
#pragma unroll
        for (int c = 0; c < 4; c++) {
            int j = tx * 2 + 32 * c;
            float2 f;
            memcpy(&f, &acc[u][c], 8);
            float2 bb = *reinterpret_cast<const float2*>(bias + col0 + j);
            f.x += bb.x;
            f.y += bb.y;
            *reinterpret_cast<float2*>(&g_h[row * 512 + col0 + j]) = f;
        }
    }
}

// ---------------- Kernel 3: LayerNorm + exact GELU ----------------
__global__ void __launch_bounds__(128) k3_kernel(const float* __restrict__ gamma,
                                                 const float* __restrict__ beta,
                                                 float* __restrict__ out) {
    __shared__ float red[8];
    const size_t row = blockIdx.x;
    const int tid = threadIdx.x;
    const int warp = tid >> 5, lane = tid & 31;
    const float* h = g_h + row * 512;

    float4 x = *reinterpret_cast<const float4*>(h + tid * 4);
    float s = x.x + x.y + x.z + x.w;
#pragma unroll
    for (int o = 16; o > 0; o >>= 1) s += __shfl_xor_sync(0xffffffffu, s, o);
    if (lane == 0) red[warp] = s;
    __syncthreads();
    float mu = (red[0] + red[1] + red[2] + red[3]) * (1.f / 512.f);

    float dx0 = x.x - mu, dx1 = x.y - mu, dx2 = x.z - mu, dx3 = x.w - mu;
    float q = dx0 * dx0 + dx1 * dx1 + dx2 * dx2 + dx3 * dx3;
#pragma unroll
    for (int o = 16; o > 0; o >>= 1) q += __shfl_xor_sync(0xffffffffu, q, o);
    if (lane == 0) red[4 + warp] = q;
    __syncthreads();
    float var = (red[4] + red[5] + red[6] + red[7]) * (1.f / 512.f);
    float rstd = rsqrtf(var + LN_EPS);

    float4 g = *reinterpret_cast<const float4*>(gamma + tid * 4);
    float4 b = *reinterpret_cast<const float4*>(beta + tid * 4);
    float y0 = dx0 * rstd * g.x + b.x;
    float y1 = dx1 * rstd * g.y + b.y;
    float y2 = dx2 * rstd * g.z + b.z;
    float y3 = dx3 * rstd * g.w + b.w;

    const float invs2 = 0.70710678118654752f;
    float4 o4;
    o4.x = y0 * 0.5f * (1.f + erff(y0 * invs2));
    o4.y = y1 * 0.5f * (1.f + erff(y1 * invs2));
    o4.z = y2 * 0.5f * (1.f + erff(y2 * invs2));
    o4.w = y3 * 0.5f * (1.f + erff(y3 * invs2));
    *reinterpret_cast<float4*>(out + row * 512 + tid * 4) = o4;
}

// ---------------- launch ----------------
extern "C" void kernel_launch(void* const* d_in, const int* in_sizes, int n_in,
                              void* d_out, int out_size) {
    const float* v     = (const float*)d_in[0];
    const float* Wd    = (const float*)d_in[1];
    const float* We    = (const float*)d_in[2];
    const float* Wl    = (const float*)d_in[3];
    const float* bl    = (const float*)d_in[4];
    const float* gamma = (const float*)d_in[5];
    const float* beta  = (const float*)d_in[6];
    float* out = (float*)d_out;

    k1_kernel<<<N_ROWS / 32, 256>>>(v, Wd, We);
    dim3 g2(N_ROWS / 128, 4);
    k2_kernel<<<g2, 256>>>(Wl, bl);
    k3_kernel<<<N_ROWS, 128>>>(gamma, beta, out);
}

// round 4
// speedup vs baseline: 2.1444x; 2.1444x over previous
#include <cuda_runtime.h>
#include <cuda_bf16.h>
#include <math.h>
#include <stdint.h>

#define NR 131072
#define EPS_N 1e-3f
#define LN_EPS 1e-5f

// ---- global scratch (allocation-free) ----
__device__ __nv_bfloat16 g_wdh[128 * 512], g_wdl[128 * 512];
__device__ __nv_bfloat16 g_wlh[512 * 512], g_wll[512 * 512];
__device__ __nv_bfloat16 g_v2h[(size_t)NR * 512], g_v2l[(size_t)NR * 512];
__device__ float g_h[(size_t)NR * 512];

__device__ __forceinline__ uint32_t pack_bf(__nv_bfloat16 a, __nv_bfloat16 b) {
    __nv_bfloat162 p(a, b);
    return *reinterpret_cast<uint32_t*>(&p);
}
__device__ __forceinline__ void split4(float4 x, uint32_t& h0, uint32_t& h1, uint32_t& l0, uint32_t& l1) {
    __nv_bfloat16 a = __float2bfloat16_rn(x.x), b = __float2bfloat16_rn(x.y);
    __nv_bfloat16 c = __float2bfloat16_rn(x.z), d = __float2bfloat16_rn(x.w);
    __nv_bfloat16 ra = __float2bfloat16_rn(x.x - __bfloat162float(a));
    __nv_bfloat16 rb = __float2bfloat16_rn(x.y - __bfloat162float(b));
    __nv_bfloat16 rc = __float2bfloat16_rn(x.z - __bfloat162float(c));
    __nv_bfloat16 rd = __float2bfloat16_rn(x.w - __bfloat162float(d));
    h0 = pack_bf(a, b); h1 = pack_bf(c, d);
    l0 = pack_bf(ra, rb); l1 = pack_bf(rc, rd);
}

__device__ __forceinline__ void mma_bf16(float* c, uint32_t a0, uint32_t a1, uint32_t a2, uint32_t a3,
                                         uint32_t b0, uint32_t b1) {
    asm volatile("mma.sync.aligned.m16n8k16.row.col.f32.bf16.bf16.f32 "
                 "{%0,%1,%2,%3},{%4,%5,%6,%7},{%8,%9},{%0,%1,%2,%3};"
                 : "+f"(c[0]), "+f"(c[1]), "+f"(c[2]), "+f"(c[3])
                 : "r"(a0), "r"(a1), "r"(a2), "r"(a3), "r"(b0), "r"(b1));
}

// ---------------- prep: split weights to bf16 hi/lo ----------------
__global__ void __launch_bounds__(256) kprep(const float* __restrict__ Wd,
                                             const float* __restrict__ Wl) {
    int i = blockIdx.x * 256 + threadIdx.x;
    if (i < 128 * 512) {
        float x = Wd[i];
        __nv_bfloat16 h = __float2bfloat16_rn(x);
        g_wdh[i] = h;
        g_wdl[i] = __float2bfloat16_rn(x - __bfloat162float(h));
    }
    if (i < 512 * 512) {
        float x = Wl[i];
        __nv_bfloat16 h = __float2bfloat16_rn(x);
        g_wlh[i] = h;
        g_wll[i] = __float2bfloat16_rn(x - __bfloat162float(h));
    }
}

// ---------------- Kernel 1: HMMA GEMM1 + scalarizer epilogue ----------------
// CTA: 64 v-rows = 192 A-rows, N=128, K=512 in chunks of 64. 512 threads.
// Warp grid 4(M)x4(N): warp tile 48x32. Split passes: AhBh, AhBl, AlBh.
#define AST 36                 // smem row stride in uint32 (conflict-free frags)
#define K1_WE 0                // 384 floats = 1536B
#define K1_BUF 1536
#define K1_AH (K1_BUF)
#define K1_AL (K1_AH + 192 * AST * 4)
#define K1_BH (K1_AL + 192 * AST * 4)
#define K1_BL (K1_BH + 128 * AST * 4)
#define VST 132                // vred row stride (floats)
#define K1_SMEM (K1_BUF + 192 * VST * 4)   // union(A/B, vred); vred is bigger

__global__ void __launch_bounds__(512) k1_kernel(const float* __restrict__ v,
                                                 const float* __restrict__ We) {
    extern __shared__ char smem[];
    float* sWe = (float*)(smem + K1_WE);
    uint32_t* Ah = (uint32_t*)(smem + K1_AH);
    uint32_t* Al = (uint32_t*)(smem + K1_AL);
    uint32_t* Bh = (uint32_t*)(smem + K1_BH);
    uint32_t* Bl = (uint32_t*)(smem + K1_BL);
    float* vred = (float*)(smem + K1_BUF);

    const int tid = threadIdx.x;
    const int wid = tid >> 5, lane = tid & 31;
    const int wm = wid & 3, wn = wid >> 2;           // warp grid 4x4
    const int fr = lane >> 2, fc = lane & 3;         // frag row/col
    const int blk = blockIdx.x;
    const float* vbase = v + (size_t)blk * 192 * 512;

    for (int i = tid; i < 384; i += 512) sWe[i] = We[i];

    float acc[3][4][4];
#pragma unroll
    for (int m = 0; m < 3; m++)
#pragma unroll
        for (int n = 0; n < 4; n++)
#pragma unroll
            for (int j = 0; j < 4; j++) acc[m][n][j] = 0.f;

    for (int c0 = 0; c0 < 8; c0++) {
        const int k0 = c0 * 64;
        float4 va[6];
        uint4 vb[4];
#pragma unroll
        for (int t = 0; t < 6; t++) {
            int lin = tid + 512 * t;
            int g = lin >> 4, q = lin & 15;
            va[t] = *(const float4*)(vbase + (size_t)g * 512 + k0 + q * 4);
        }
#pragma unroll
        for (int t = 0; t < 4; t++) {
            int lin = tid + 512 * t;
            int tile = lin >> 10, rem = lin & 1023, j = rem >> 3, q = rem & 7;
            vb[t] = *(const uint4*)((tile ? g_wdl : g_wdh) + j * 512 + k0 + q * 8);
        }
        __syncthreads();
#pragma unroll
        for (int t = 0; t < 6; t++) {
            int lin = tid + 512 * t;
            int g = lin >> 4, q = lin & 15;
            uint32_t h0, h1, l0, l1;
            split4(va[t], h0, h1, l0, l1);
            *(uint2*)(Ah + g * AST + 2 * q) = make_uint2(h0, h1);
            *(uint2*)(Al + g * AST + 2 * q) = make_uint2(l0, l1);
        }
#pragma unroll
        for (int t = 0; t < 4; t++) {
            int lin = tid + 512 * t;
            int tile = lin >> 10, rem = lin & 1023, j = rem >> 3, q = rem & 7;
            *(uint4*)((tile ? Bl : Bh) + j * AST + 4 * q) = vb[t];
        }
        __syncthreads();
#pragma unroll
        for (int p = 0; p < 3; p++) {
            const uint32_t* As = (p == 2) ? Al : Ah;
            const uint32_t* Bs = (p == 1) ? Bl : Bh;
#pragma unroll
            for (int ks = 0; ks < 4; ks++) {
                uint32_t a[3][4], b[4][2];
#pragma unroll
                for (int m = 0; m < 3; m++) {
                    const uint32_t* base = As + (wm * 48 + m * 16 + fr) * AST + ks * 8 + fc;
                    a[m][0] = base[0];
                    a[m][1] = base[8 * AST];
                    a[m][2] = base[4];
                    a[m][3] = base[8 * AST + 4];
                }
#pragma unroll
                for (int n = 0; n < 4; n++) {
                    const uint32_t* base = Bs + (wn * 32 + n * 8 + fr) * AST + ks * 8 + fc;
                    b[n][0] = base[0];
                    b[n][1] = base[4];
                }
#pragma unroll
                for (int m = 0; m < 3; m++)
#pragma unroll
                    for (int n = 0; n < 4; n++)
                        mma_bf16(acc[m][n], a[m][0], a[m][1], a[m][2], a[m][3], b[n][0], b[n][1]);
            }
        }
        __syncthreads();
    }
    // dump acc -> vred (row stride VST)
#pragma unroll
    for (int m = 0; m < 3; m++) {
        int row = wm * 48 + m * 16 + fr;
#pragma unroll
        for (int n = 0; n < 4; n++) {
            int col = wn * 32 + n * 8 + fc * 2;
            *(float2*)(vred + row * VST + col) = make_float2(acc[m][n][0], acc[m][n][1]);
            *(float2*)(vred + (row + 8) * VST + col) = make_float2(acc[m][n][2], acc[m][n][3]);
        }
    }
    __syncthreads();

    // ---- epilogue: 16 warps x 4 rows; lane owns cols lane+32c ----
    float we[3][4];
#pragma unroll
    for (int e = 0; e < 3; e++)
#pragma unroll
        for (int c = 0; c < 4; c++) we[e][c] = sWe[e * 128 + lane + 32 * c];

    for (int t = 0; t < 4; t++) {
        int r = wid + 16 * t;            // v-row within CTA (0..63)
        size_t gr = (size_t)blk * 64 + r;
        float vr[3][4];
#pragma unroll
        for (int i = 0; i < 3; i++)
#pragma unroll
            for (int c = 0; c < 4; c++)
                vr[i][c] = vred[(r * 3 + i) * VST + lane + 32 * c];

        float d9[3][3];
#pragma unroll
        for (int i = 0; i < 3; i++)
#pragma unroll
            for (int e = 0; e < 3; e++) {
                float s = 0.f;
#pragma unroll
                for (int c = 0; c < 4; c++) s = fmaf(vr[i][c], we[e][c], s);
#pragma unroll
                for (int o = 16; o > 0; o >>= 1) s += __shfl_xor_sync(0xffffffffu, s, o);
                d9[i][e] = s;
            }
        float nd[3][3];
#pragma unroll
        for (int e = 0; e < 3; e++) {
            float dn = sqrtf(d9[0][e] * d9[0][e] + d9[1][e] * d9[1][e] + d9[2][e] * d9[2][e]);
            float inv = 1.f / (dn + EPS_N);
            nd[0][e] = d9[0][e] * inv;
            nd[1][e] = d9[1][e] * inv;
            nd[2][e] = d9[2][e] * inv;
        }
        __nv_bfloat16* oh = g_v2h + gr * 512;
        __nv_bfloat16* ol = g_v2l + gr * 512;
#pragma unroll
        for (int c = 0; c < 4; c++) {
            float n = sqrtf(vr[0][c] * vr[0][c] + vr[1][c] * vr[1][c] + vr[2][c] * vr[2][c]);
            float invn = 1.f / (n + EPS_N);
            int k = lane + 32 * c;
            float vals[4];
            vals[0] = n;
#pragma unroll
            for (int e = 0; e < 3; e++)
                vals[1 + e] = (vr[0][c] * nd[0][e] + vr[1][c] * nd[1][e] + vr[2][c] * nd[2][e]) * invn;
#pragma unroll
            for (int seg = 0; seg < 4; seg++) {
                int idx = seg * 128 + k;
                __nv_bfloat16 h = __float2bfloat16_rn(vals[seg]);
                oh[idx] = h;
                ol[idx] = __float2bfloat16_rn(vals[seg] - __bfloat162float(h));
            }
        }
    }
}

// ---------------- Kernel 2: HMMA GEMM2 (H = v2 @ Wl^T + b) ----------------
// CTA 256x128, K=512 chunks of 64. 512 threads, warp grid 4x4 (64x32 tiles).
#define K2_AH 0
#define K2_AL (K2_AH + 256 * AST * 4)
#define K2_BH (K2_AL + 256 * AST * 4)
#define K2_BL (K2_BH + 128 * AST * 4)
#define K2_SMEM (K2_BL + 128 * AST * 4)

__global__ void __launch_bounds__(512) k2_kernel(const float* __restrict__ bias) {
    extern __shared__ char smem[];
    uint32_t* Ah = (uint32_t*)(smem + K2_AH);
    uint32_t* Al = (uint32_t*)(smem + K2_AL);
    uint32_t* Bh = (uint32_t*)(smem + K2_BH);
    uint32_t* Bl = (uint32_t*)(smem + K2_BL);

    const int tid = threadIdx.x;
    const int wid = tid >> 5, lane = tid & 31;
    const int wm = wid & 3, wn = wid >> 2;
    const int fr = lane >> 2, fc = lane & 3;
    const int col0 = blockIdx.x * 128;
    const size_t row0 = (size_t)blockIdx.y * 256;

    float acc[4][4][4];
#pragma unroll
    for (int m = 0; m < 4; m++)
#pragma unroll
        for (int n = 0; n < 4; n++)
#pragma unroll
            for (int j = 0; j < 4; j++) acc[m][n][j] = 0.f;

    for (int c0 = 0; c0 < 8; c0++) {
        const int k0 = c0 * 64;
        uint4 vab[8], vb[4];
#pragma unroll
        for (int t = 0; t < 8; t++) {
            int lin = tid + 512 * t;
            int tile = lin >> 11, rem = lin & 2047, r = rem >> 3, q = rem & 7;
            vab[t] = *(const uint4*)((tile ? g_v2l : g_v2h) + (row0 + r) * 512 + k0 + q * 8);
        }
#pragma unroll
        for (int t = 0; t < 4; t++) {
            int lin = tid + 512 * t;
            int tile = lin >> 10, rem = lin & 1023, r = rem >> 3, q = rem & 7;
            vb[t] = *(const uint4*)((tile ? g_wll : g_wlh) + (size_t)(col0 + r) * 512 + k0 + q * 8);
        }
        __syncthreads();
#pragma unroll
        for (int t = 0; t < 8; t++) {
            int lin = tid + 512 * t;
            int tile = lin >> 11, rem = lin & 2047, r = rem >> 3, q = rem & 7;
            *(uint4*)((tile ? Al : Ah) + r * AST + 4 * q) = vab[t];
        }
#pragma unroll
        for (int t = 0; t < 4; t++) {
            int lin = tid + 512 * t;
            int tile = lin >> 10, rem = lin & 1023, r = rem >> 3, q = rem & 7;
            *(uint4*)((tile ? Bl : Bh) + r * AST + 4 * q) = vb[t];
        }
        __syncthreads();
#pragma unroll
        for (int p = 0; p < 3; p++) {
            const uint32_t* As = (p == 2) ? Al : Ah;
            const uint32_t* Bs = (p == 1) ? Bl : Bh;
#pragma unroll
            for (int ks = 0; ks < 4; ks++) {
                uint32_t a[4][4], b[4][2];
#pragma unroll
                for (int m = 0; m < 4; m++) {
                    const uint32_t* base = As + (wm * 64 + m * 16 + fr) * AST + ks * 8 + fc;
                    a[m][0] = base[0];
                    a[m][1] = base[8 * AST];
                    a[m][2] = base[4];
                    a[m][3] = base[8 * AST + 4];
                }
#pragma unroll
                for (int n = 0; n < 4; n++) {
                    const uint32_t* base = Bs + (wn * 32 + n * 8 + fr) * AST + ks * 8 + fc;
                    b[n][0] = base[0];
                    b[n][1] = base[4];
                }
#pragma unroll
                for (int m = 0; m < 4; m++)
#pragma unroll
                    for (int n = 0; n < 4; n++)
                        mma_bf16(acc[m][n], a[m][0], a[m][1], a[m][2], a[m][3], b[n][0], b[n][1]);
            }
        }
        __syncthreads();
    }
    // epilogue: bias add, store fp32 H
#pragma unroll
    for (int m = 0; m < 4; m++) {
        size_t row = row0 + wm * 64 + m * 16 + fr;
#pragma unroll
        for (int n = 0; n < 4; n++) {
            int col = col0 + wn * 32 + n * 8 + fc * 2;
            float2 bb = *(const float2*)(bias + col);
            *(float2*)(g_h + row * 512 + col) = make_float2(acc[m][n][0] + bb.x, acc[m][n][1] + bb.y);
            *(float2*)(g_h + (row + 8) * 512 + col) = make_float2(acc[m][n][2] + bb.x, acc[m][n][3] + bb.y);
        }
    }
}

// ---------------- Kernel 3: LayerNorm + exact GELU ----------------
__global__ void __launch_bounds__(128) k3_kernel(const float* __restrict__ gamma,
                                                 const float* __restrict__ beta,
                                                 float* __restrict__ out) {
    __shared__ float red[8];
    const size_t row = blockIdx.x;
    const int tid = threadIdx.x;
    const int warp = tid >> 5, lane = tid & 31;
    const float* h = g_h + row * 512;

    float4 x = *reinterpret_cast<const float4*>(h + tid * 4);
    float s = x.x + x.y + x.z + x.w;
#pragma unroll
    for (int o = 16; o > 0; o >>= 1) s += __shfl_xor_sync(0xffffffffu, s, o);
    if (lane == 0) red[warp] = s;
    __syncthreads();
    float mu = (red[0] + red[1] + red[2] + red[3]) * (1.f / 512.f);

    float dx0 = x.x - mu, dx1 = x.y - mu, dx2 = x.z - mu, dx3 = x.w - mu;
    float q = dx0 * dx0 + dx1 * dx1 + dx2 * dx2 + dx3 * dx3;
#pragma unroll
    for (int o = 16; o > 0; o >>= 1) q += __shfl_xor_sync(0xffffffffu, q, o);
    if (lane == 0) red[4 + warp] = q;
    __syncthreads();
    float var = (red[4] + red[5] + red[6] + red[7]) * (1.f / 512.f);
    float rstd = rsqrtf(var + LN_EPS);

    float4 g = *reinterpret_cast<const float4*>(gamma + tid * 4);
    float4 b = *reinterpret_cast<const float4*>(beta + tid * 4);
    float y0 = dx0 * rstd * g.x + b.x;
    float y1 = dx1 * rstd * g.y + b.y;
    float y2 = dx2 * rstd * g.z + b.z;
    float y3 = dx3 * rstd * g.w + b.w;

    const float invs2 = 0.70710678118654752f;
    float4 o4;
    o4.x = y0 * 0.5f * (1.f + erff(y0 * invs2));
    o4.y = y1 * 0.5f * (1.f + erff(y1 * invs2));
    o4.z = y2 * 0.5f * (1.f + erff(y2 * invs2));
    o4.w = y3 * 0.5f * (1.f + erff(y3 * invs2));
    *reinterpret_cast<float4*>(out + row * 512 + tid * 4) = o4;
}

// ---------------- launch ----------------
extern "C" void kernel_launch(void* const* d_in, const int* in_sizes, int n_in,
                              void* d_out, int out_size) {
    const float* v     = (const float*)d_in[0];
    const float* Wd    = (const float*)d_in[1];
    const float* We    = (const float*)d_in[2];
    const float* Wl    = (const float*)d_in[3];
    const float* bl    = (const float*)d_in[4];
    const float* gamma = (const float*)d_in[5];
    const float* beta  = (const float*)d_in[6];
    float* out = (float*)d_out;

    static int inited = 0;
    if (!inited) {
        cudaFuncSetAttribute(k1_kernel, cudaFuncAttributeMaxDynamicSharedMemorySize, K1_SMEM);
        cudaFuncSetAttribute(k2_kernel, cudaFuncAttributeMaxDynamicSharedMemorySize, K2_SMEM);
        inited = 1;
    }

    kprep<<<1024, 256>>>(Wd, Wl);
    k1_kernel<<<NR / 64, 512, K1_SMEM>>>(v, We);
    dim3 g2(4, NR / 256);
    k2_kernel<<<g2, 512, K2_SMEM>>>(bl);
    k3_kernel<<<NR, 128>>>(gamma, beta, out);
}

// round 5
// speedup vs baseline: 2.4027x; 1.1204x over previous
#include <cuda_runtime.h>
#include <cuda_bf16.h>
#include <math.h>
#include <stdint.h>

#define NR 131072
#define EPS_N 1e-3f
#define LN_EPS 1e-5f

// ---- global scratch (allocation-free) ----
__device__ __nv_bfloat16 g_wdh[128 * 512], g_wdl[128 * 512];
__device__ __nv_bfloat16 g_wlh[512 * 512], g_wll[512 * 512];
__device__ __nv_bfloat16 g_v2h[(size_t)NR * 512], g_v2l[(size_t)NR * 512];

// ---- helpers ----
__device__ __forceinline__ uint32_t smem_u32(const void* p) {
    uint32_t a;
    asm("{ .reg .u64 t; cvta.to.shared.u64 t, %1; cvt.u32.u64 %0, t; }" : "=r"(a) : "l"(p));
    return a;
}
__device__ __forceinline__ uint32_t pack_bf(__nv_bfloat16 a, __nv_bfloat16 b) {
    __nv_bfloat162 p(a, b);
    return *reinterpret_cast<uint32_t*>(&p);
}
__device__ __forceinline__ void split4(float4 x, uint32_t& h0, uint32_t& h1, uint32_t& l0, uint32_t& l1) {
    __nv_bfloat16 a = __float2bfloat16_rn(x.x), b = __float2bfloat16_rn(x.y);
    __nv_bfloat16 c = __float2bfloat16_rn(x.z), d = __float2bfloat16_rn(x.w);
    __nv_bfloat16 ra = __float2bfloat16_rn(x.x - __bfloat162float(a));
    __nv_bfloat16 rb = __float2bfloat16_rn(x.y - __bfloat162float(b));
    __nv_bfloat16 rc = __float2bfloat16_rn(x.z - __bfloat162float(c));
    __nv_bfloat16 rd = __float2bfloat16_rn(x.w - __bfloat162float(d));
    h0 = pack_bf(a, b); h1 = pack_bf(c, d);
    l0 = pack_bf(ra, rb); l1 = pack_bf(rc, rd);
}
__device__ __forceinline__ void mma_bf16(float* c, uint32_t a0, uint32_t a1, uint32_t a2, uint32_t a3,
                                         uint32_t b0, uint32_t b1) {
    asm volatile("mma.sync.aligned.m16n8k16.row.col.f32.bf16.bf16.f32 "
                 "{%0,%1,%2,%3},{%4,%5,%6,%7},{%8,%9},{%0,%1,%2,%3};"
                 : "+f"(c[0]), "+f"(c[1]), "+f"(c[2]), "+f"(c[3])
                 : "r"(a0), "r"(a1), "r"(a2), "r"(a3), "r"(b0), "r"(b1));
}
#define LDSM4(R, A) \
    asm volatile("ldmatrix.sync.aligned.m8n8.x4.shared.b16 {%0,%1,%2,%3},[%4];" \
                 : "=r"((R)[0]), "=r"((R)[1]), "=r"((R)[2]), "=r"((R)[3]) : "r"(A))
#define CP16(dst, src) asm volatile("cp.async.ca.shared.global [%0],[%1],16;" :: "r"(dst), "l"(src) : "memory")
#define CPCOMMIT()     asm volatile("cp.async.commit_group;" ::: "memory")
#define CPWAIT0()      asm volatile("cp.async.wait_group 0;" ::: "memory")

// ---------------- prep: split weights to bf16 hi/lo ----------------
__global__ void __launch_bounds__(256) kprep(const float* __restrict__ Wd,
                                             const float* __restrict__ Wl) {
    int i = blockIdx.x * 256 + threadIdx.x;
    if (i < 128 * 512) {
        float x = Wd[i];
        __nv_bfloat16 h = __float2bfloat16_rn(x);
        g_wdh[i] = h;
        g_wdl[i] = __float2bfloat16_rn(x - __bfloat162float(h));
    }
    if (i < 512 * 512) {
        float x = Wl[i];
        __nv_bfloat16 h = __float2bfloat16_rn(x);
        g_wlh[i] = h;
        g_wll[i] = __float2bfloat16_rn(x - __bfloat162float(h));
    }
}

// ---------------- Kernel 1: HMMA GEMM1 + scalarizer epilogue ----------------
// CTA: 64 v-rows = 192 A-rows, N=128, K chunks of 32, double-buffered.
// 512 threads, warp grid 4(M)x4(N): warp tile 48x32.
// Row stride 80B (32 bf16 + 16B pad) -> conflict-free ldmatrix.
#define K1_AH(b) (1536 + (b) * 15360)
#define K1_AL(b) (32256 + (b) * 15360)
#define K1_BH(b) (62976 + (b) * 10240)
#define K1_BL(b) (83456 + (b) * 10240)
#define K1_SMEM 103936
#define VST 132

__global__ void __launch_bounds__(512) k1_kernel(const float* __restrict__ v,
                                                 const float* __restrict__ We) {
    extern __shared__ char smem[];
    const uint32_t sb = smem_u32(smem);
    const int tid = threadIdx.x, wid = tid >> 5, lane = tid & 31;
    const int wm = wid & 3, wn = wid >> 2;
    const int fr = lane >> 2, fc = lane & 3;
    const int lr = lane & 7, b8 = (lane >> 3) & 1, b16 = (lane >> 4) & 1;
    const int blk = blockIdx.x;
    const float* vbase = v + (size_t)blk * 192 * 512;

    float* sWe = (float*)smem;
    for (int i = tid; i < 384; i += 512) sWe[i] = We[i];

    // cp.async B mapping (1 chunk16 per matrix per thread)
    const int brow = tid >> 2, bseg = tid & 3;
    const uint32_t bdst = (uint32_t)(brow * 80 + bseg * 16);
    const __nv_bfloat16* bsrc_h = g_wdh + brow * 512 + bseg * 8;
    const __nv_bfloat16* bsrc_l = g_wdl + brow * 512 + bseg * 8;

    // ldmatrix per-lane offsets
    const uint32_t aoff = (uint32_t)((wm * 48 + lr + b8 * 8) * 80 + b16 * 16);
    const uint32_t boff = (uint32_t)((wn * 32 + lr + b8 * 8) * 80 + b16 * 16);

    float acc[3][4][4];
#pragma unroll
    for (int m = 0; m < 3; m++)
#pragma unroll
        for (int n = 0; n < 4; n++)
#pragma unroll
            for (int j = 0; j < 4; j++) acc[m][n][j] = 0.f;

    float4 va[3];
    // prologue: chunk 0
    CP16(sb + K1_BH(0) + bdst, bsrc_h);
    CP16(sb + K1_BL(0) + bdst, bsrc_l);
    CPCOMMIT();
#pragma unroll
    for (int t = 0; t < 3; t++) {
        int lin = tid + 512 * t;
        int g = lin >> 3, q = lin & 7;
        va[t] = *(const float4*)(vbase + (size_t)g * 512 + q * 4);
    }
#pragma unroll
    for (int t = 0; t < 3; t++) {
        int lin = tid + 512 * t;
        int g = lin >> 3, q = lin & 7;
        uint32_t h0, h1, l0, l1;
        split4(va[t], h0, h1, l0, l1);
        *(uint2*)(smem + K1_AH(0) + g * 80 + q * 8) = make_uint2(h0, h1);
        *(uint2*)(smem + K1_AL(0) + g * 80 + q * 8) = make_uint2(l0, l1);
    }
    CPWAIT0();
    __syncthreads();

    int cur = 0;
    for (int c = 0; c < 16; c++) {
        if (c < 15) {
            const int k0n = (c + 1) * 32;
            CP16(sb + K1_BH(cur ^ 1) + bdst, bsrc_h + k0n);
            CP16(sb + K1_BL(cur ^ 1) + bdst, bsrc_l + k0n);
            CPCOMMIT();
#pragma unroll
            for (int t = 0; t < 3; t++) {
                int lin = tid + 512 * t;
                int g = lin >> 3, q = lin & 7;
                va[t] = *(const float4*)(vbase + (size_t)g * 512 + k0n + q * 4);
            }
        }
        const uint32_t Ah = sb + K1_AH(cur), Al = sb + K1_AL(cur);
        const uint32_t Bh = sb + K1_BH(cur), Bl = sb + K1_BL(cur);
#pragma unroll
        for (int ks = 0; ks < 2; ks++) {
            uint32_t ah[3][4], bh[2][4];
#pragma unroll
            for (int m = 0; m < 3; m++) LDSM4(ah[m], Ah + aoff + m * 1280 + ks * 32);
#pragma unroll
            for (int p = 0; p < 2; p++) LDSM4(bh[p], Bh + boff + p * 1280 + ks * 32);
#pragma unroll
            for (int m = 0; m < 3; m++)
#pragma unroll
                for (int n = 0; n < 4; n++)
                    mma_bf16(acc[m][n], ah[m][0], ah[m][1], ah[m][2], ah[m][3],
                             bh[n >> 1][n & 1], bh[n >> 1][2 + (n & 1)]);
            uint32_t al[3][4];
#pragma unroll
            for (int m = 0; m < 3; m++) LDSM4(al[m], Al + aoff + m * 1280 + ks * 32);
#pragma unroll
            for (int m = 0; m < 3; m++)
#pragma unroll
                for (int n = 0; n < 4; n++)
                    mma_bf16(acc[m][n], al[m][0], al[m][1], al[m][2], al[m][3],
                             bh[n >> 1][n & 1], bh[n >> 1][2 + (n & 1)]);
            uint32_t bl[2][4];
#pragma unroll
            for (int p = 0; p < 2; p++) LDSM4(bl[p], Bl + boff + p * 1280 + ks * 32);
#pragma unroll
            for (int m = 0; m < 3; m++)
#pragma unroll
                for (int n = 0; n < 4; n++)
                    mma_bf16(acc[m][n], ah[m][0], ah[m][1], ah[m][2], ah[m][3],
                             bl[n >> 1][n & 1], bl[n >> 1][2 + (n & 1)]);
        }
        if (c < 15) {
#pragma unroll
            for (int t = 0; t < 3; t++) {
                int lin = tid + 512 * t;
                int g = lin >> 3, q = lin & 7;
                uint32_t h0, h1, l0, l1;
                split4(va[t], h0, h1, l0, l1);
                *(uint2*)(smem + K1_AH(cur ^ 1) + g * 80 + q * 8) = make_uint2(h0, h1);
                *(uint2*)(smem + K1_AL(cur ^ 1) + g * 80 + q * 8) = make_uint2(l0, l1);
            }
            CPWAIT0();
        }
        __syncthreads();
        cur ^= 1;
    }

    // dump acc -> vred (union over the operand buffers; safe after final sync)
    float* vred = (float*)(smem + 1536);
#pragma unroll
    for (int m = 0; m < 3; m++) {
        int row = wm * 48 + m * 16 + fr;
#pragma unroll
        for (int n = 0; n < 4; n++) {
            int col = wn * 32 + n * 8 + fc * 2;
            *(float2*)(vred + row * VST + col) = make_float2(acc[m][n][0], acc[m][n][1]);
            *(float2*)(vred + (row + 8) * VST + col) = make_float2(acc[m][n][2], acc[m][n][3]);
        }
    }
    __syncthreads();

    // ---- epilogue: norms, directions, projections -> v2 (hi/lo bf16) ----
    float we[3][4];
#pragma unroll
    for (int e = 0; e < 3; e++)
#pragma unroll
        for (int c = 0; c < 4; c++) we[e][c] = sWe[e * 128 + lane + 32 * c];

    for (int t = 0; t < 4; t++) {
        int r = wid + 16 * t;
        size_t gr = (size_t)blk * 64 + r;
        float vr[3][4];
#pragma unroll
        for (int i = 0; i < 3; i++)
#pragma unroll
            for (int c = 0; c < 4; c++)
                vr[i][c] = vred[(r * 3 + i) * VST + lane + 32 * c];

        float d9[3][3];
#pragma unroll
        for (int i = 0; i < 3; i++)
#pragma unroll
            for (int e = 0; e < 3; e++) {
                float s = 0.f;
#pragma unroll
                for (int c = 0; c < 4; c++) s = fmaf(vr[i][c], we[e][c], s);
#pragma unroll
                for (int o = 16; o > 0; o >>= 1) s += __shfl_xor_sync(0xffffffffu, s, o);
                d9[i][e] = s;
            }
        float nd[3][3];
#pragma unroll
        for (int e = 0; e < 3; e++) {
            float dn = sqrtf(d9[0][e] * d9[0][e] + d9[1][e] * d9[1][e] + d9[2][e] * d9[2][e]);
            float inv = 1.f / (dn + EPS_N);
            nd[0][e] = d9[0][e] * inv;
            nd[1][e] = d9[1][e] * inv;
            nd[2][e] = d9[2][e] * inv;
        }
        __nv_bfloat16* oh = g_v2h + gr * 512;
        __nv_bfloat16* ol = g_v2l + gr * 512;
#pragma unroll
        for (int c = 0; c < 4; c++) {
            float n = sqrtf(vr[0][c] * vr[0][c] + vr[1][c] * vr[1][c] + vr[2][c] * vr[2][c]);
            float invn = 1.f / (n + EPS_N);
            int k = lane + 32 * c;
            float vals[4];
            vals[0] = n;
#pragma unroll
            for (int e = 0; e < 3; e++)
                vals[1 + e] = (vr[0][c] * nd[0][e] + vr[1][c] * nd[1][e] + vr[2][c] * nd[2][e]) * invn;
#pragma unroll
            for (int seg = 0; seg < 4; seg++) {
                int idx = seg * 128 + k;
                __nv_bfloat16 h = __float2bfloat16_rn(vals[seg]);
                oh[idx] = h;
                ol[idx] = __float2bfloat16_rn(vals[seg] - __bfloat162float(h));
            }
        }
    }
}

// ---------------- Kernel 2: HMMA GEMM2 fused with LayerNorm+GELU ----------------
// CTA: 64 rows x full 512 cols. 512 threads, warp grid 2(M)x8(N): tile 32x64.
#define K2_AH(b) ((b) * 5120)
#define K2_AL(b) (10240 + (b) * 5120)
#define K2_BH(b) (20480 + (b) * 40960)
#define K2_BL(b) (102400 + (b) * 40960)
#define K2_PSUM 184320
#define K2_PSQ 186368
#define K2_SMEM 188416

__global__ void __launch_bounds__(512) k2_kernel(const float* __restrict__ bias,
                                                 const float* __restrict__ gamma,
                                                 const float* __restrict__ beta,
                                                 float* __restrict__ out) {
    extern __shared__ char smem[];
    const uint32_t sb = smem_u32(smem);
    const int tid = threadIdx.x, wid = tid >> 5, lane = tid & 31;
    const int wm = wid & 1, wn = wid >> 1;
    const int fr = lane >> 2, fc = lane & 3;
    const int lr = lane & 7, b8 = (lane >> 3) & 1, b16 = (lane >> 4) & 1;
    const size_t row0 = (size_t)blockIdx.x * 64;

    // cp.async mappings
    const int arow = (tid >> 2) & 63, aseg = tid & 3, alo = tid >> 8;
    const __nv_bfloat16* asrc = (alo ? g_v2l : g_v2h) + (row0 + arow) * 512 + aseg * 8;
    const uint32_t adst = (alo ? 10240u : 0u) + (uint32_t)(arow * 80 + aseg * 16);

    const uint32_t aoff = (uint32_t)((wm * 32 + lr + b8 * 8) * 80 + b16 * 16);
    const uint32_t boff = (uint32_t)((wn * 64 + lr + b8 * 8) * 80 + b16 * 16);

    float acc[2][8][4];
#pragma unroll
    for (int m = 0; m < 2; m++)
#pragma unroll
        for (int n = 0; n < 8; n++)
#pragma unroll
            for (int j = 0; j < 4; j++) acc[m][n][j] = 0.f;

    // prologue: chunk 0
    {
        CP16(sb + K2_AH(0) + adst, asrc);
#pragma unroll
        for (int i = 0; i < 8; i++) {
            int lin = tid + 512 * i;
            int mat = lin >> 11, rem = lin & 2047, r = rem >> 2, seg = rem & 3;
            const __nv_bfloat16* src = (mat ? g_wll : g_wlh) + (size_t)r * 512 + seg * 8;
            CP16(sb + (mat ? K2_BL(0) : K2_BH(0)) + (uint32_t)(r * 80 + seg * 16), src);
        }
        CPCOMMIT();
        CPWAIT0();
        __syncthreads();
    }
    int cur = 0;
    for (int c = 0; c < 16; c++) {
        if (c < 15) {
            const int k0n = (c + 1) * 32;
            CP16(sb + (cur ? K2_AH(0) : K2_AH(1)) + adst, asrc + k0n);
#pragma unroll
            for (int i = 0; i < 8; i++) {
                int lin = tid + 512 * i;
                int mat = lin >> 11, rem = lin & 2047, r = rem >> 2, seg = rem & 3;
                const __nv_bfloat16* src = (mat ? g_wll : g_wlh) + (size_t)r * 512 + k0n + seg * 8;
                CP16(sb + (mat ? K2_BL(cur ^ 1) : K2_BH(cur ^ 1)) + (uint32_t)(r * 80 + seg * 16), src);
            }
            CPCOMMIT();
        }
        const uint32_t Ah = sb + K2_AH(cur), Al = sb + K2_AL(cur);
        const uint32_t Bh = sb + K2_BH(cur), Bl = sb + K2_BL(cur);
#pragma unroll
        for (int ks = 0; ks < 2; ks++) {
            uint32_t ah[2][4], bh[4][4];
#pragma unroll
            for (int m = 0; m < 2; m++) LDSM4(ah[m], Ah + aoff + m * 1280 + ks * 32);
#pragma unroll
            for (int p = 0; p < 4; p++) LDSM4(bh[p], Bh + boff + p * 1280 + ks * 32);
#pragma unroll
            for (int m = 0; m < 2; m++)
#pragma unroll
                for (int n = 0; n < 8; n++)
                    mma_bf16(acc[m][n], ah[m][0], ah[m][1], ah[m][2], ah[m][3],
                             bh[n >> 1][n & 1], bh[n >> 1][2 + (n & 1)]);
            uint32_t al[2][4];
#pragma unroll
            for (int m = 0; m < 2; m++) LDSM4(al[m], Al + aoff + m * 1280 + ks * 32);
#pragma unroll
            for (int m = 0; m < 2; m++)
#pragma unroll
                for (int n = 0; n < 8; n++)
                    mma_bf16(acc[m][n], al[m][0], al[m][1], al[m][2], al[m][3],
                             bh[n >> 1][n & 1], bh[n >> 1][2 + (n & 1)]);
            uint32_t bl[4][4];
#pragma unroll
            for (int p = 0; p < 4; p++) LDSM4(bl[p], Bl + boff + p * 1280 + ks * 32);
#pragma unroll
            for (int m = 0; m < 2; m++)
#pragma unroll
                for (int n = 0; n < 8; n++)
                    mma_bf16(acc[m][n], ah[m][0], ah[m][1], ah[m][2], ah[m][3],
                             bl[n >> 1][n & 1], bl[n >> 1][2 + (n & 1)]);
        }
        if (c < 15) CPWAIT0();
        __syncthreads();
        cur ^= 1;
    }

    // ---- fused epilogue: bias + LayerNorm + exact GELU ----
#pragma unroll
    for (int n = 0; n < 8; n++) {
        int col = wn * 64 + n * 8 + fc * 2;
        float2 bb = *(const float2*)(bias + col);
#pragma unroll
        for (int m = 0; m < 2; m++) {
            acc[m][n][0] += bb.x; acc[m][n][1] += bb.y;
            acc[m][n][2] += bb.x; acc[m][n][3] += bb.y;
        }
    }
    float* psum = (float*)(smem + K2_PSUM);
    float* psq  = (float*)(smem + K2_PSQ);
#pragma unroll
    for (int m = 0; m < 2; m++)
#pragma unroll
        for (int h = 0; h < 2; h++) {
            float s = 0.f, q = 0.f;
#pragma unroll
            for (int n = 0; n < 8; n++) {
                float e0 = acc[m][n][h * 2], e1 = acc[m][n][h * 2 + 1];
                s += e0 + e1;
                q += e0 * e0 + e1 * e1;
            }
            s += __shfl_xor_sync(0xffffffffu, s, 1);
            s += __shfl_xor_sync(0xffffffffu, s, 2);
            q += __shfl_xor_sync(0xffffffffu, q, 1);
            q += __shfl_xor_sync(0xffffffffu, q, 2);
            int rr = wm * 32 + m * 16 + h * 8 + fr;
            if (fc == 0) { psum[wn * 64 + rr] = s; psq[wn * 64 + rr] = q; }
        }
    __syncthreads();

    float gg[8][2], bb2[8][2];
#pragma unroll
    for (int n = 0; n < 8; n++) {
        int col = wn * 64 + n * 8 + fc * 2;
        float2 g2 = *(const float2*)(gamma + col);
        float2 b2 = *(const float2*)(beta + col);
        gg[n][0] = g2.x; gg[n][1] = g2.y;
        bb2[n][0] = b2.x; bb2[n][1] = b2.y;
    }
    const float invs2 = 0.70710678118654752f;
#pragma unroll
    for (int m = 0; m < 2; m++)
#pragma unroll
        for (int h = 0; h < 2; h++) {
            int rr = wm * 32 + m * 16 + h * 8 + fr;
            float S = 0.f, Q = 0.f;
#pragma unroll
            for (int w = 0; w < 8; w++) { S += psum[w * 64 + rr]; Q += psq[w * 64 + rr]; }
            float mu = S * (1.f / 512.f);
            float var = Q * (1.f / 512.f) - mu * mu;
            float rstd = rsqrtf(var + LN_EPS);
            size_t orow = (row0 + rr) * 512;
#pragma unroll
            for (int n = 0; n < 8; n++) {
                int col = wn * 64 + n * 8 + fc * 2;
                float y0 = (acc[m][n][h * 2] - mu) * rstd * gg[n][0] + bb2[n][0];
                float y1 = (acc[m][n][h * 2 + 1] - mu) * rstd * gg[n][1] + bb2[n][1];
                float o0 = y0 * 0.5f * (1.f + erff(y0 * invs2));
                float o1 = y1 * 0.5f * (1.f + erff(y1 * invs2));
                *(float2*)(out + orow + col) = make_float2(o0, o1);
            }
        }
}

// ---------------- launch ----------------
extern "C" void kernel_launch(void* const* d_in, const int* in_sizes, int n_in,
                              void* d_out, int out_size) {
    const float* v     = (const float*)d_in[0];
    const float* Wd    = (const float*)d_in[1];
    const float* We    = (const float*)d_in[2];
    const float* Wl    = (const float*)d_in[3];
    const float* bl    = (const float*)d_in[4];
    const float* gamma = (const float*)d_in[5];
    const float* beta  = (const float*)d_in[6];
    float* out = (float*)d_out;

    static int inited = 0;
    if (!inited) {
        cudaFuncSetAttribute(k1_kernel, cudaFuncAttributeMaxDynamicSharedMemorySize, K1_SMEM);
        cudaFuncSetAttribute(k2_kernel, cudaFuncAttributeMaxDynamicSharedMemorySize, K2_SMEM);
        inited = 1;
    }

    kprep<<<1024, 256>>>(Wd, Wl);
    k1_kernel<<<NR / 64, 512, K1_SMEM>>>(v, We);
    k2_kernel<<<NR / 64, 512, K2_SMEM>>>(bl, gamma, beta, out);
}

// round 6
// speedup vs baseline: 3.1436x; 1.3084x over previous
#include <cuda_runtime.h>
#include <cuda_fp16.h>
#include <math.h>
#include <stdint.h>

#define NR 131072
#define EPS_N 1e-3f
#define LN_EPS 1e-5f

// ---- global scratch (allocation-free) ----
__device__ __half g_wdh[128 * 512], g_wdl[128 * 512];
__device__ __half g_wlh[512 * 512], g_wll[512 * 512];
__device__ __half g_v2[(size_t)NR * 512];

// ---- helpers ----
__device__ __forceinline__ uint32_t smem_u32(const void* p) {
    uint32_t a;
    asm("{ .reg .u64 t; cvta.to.shared.u64 t, %1; cvt.u32.u64 %0, t; }" : "=r"(a) : "l"(p));
    return a;
}
__device__ __forceinline__ void mma_f16(float* c, uint32_t a0, uint32_t a1, uint32_t a2, uint32_t a3,
                                        uint32_t b0, uint32_t b1) {
    asm volatile("mma.sync.aligned.m16n8k16.row.col.f32.f16.f16.f32 "
                 "{%0,%1,%2,%3},{%4,%5,%6,%7},{%8,%9},{%0,%1,%2,%3};"
                 : "+f"(c[0]), "+f"(c[1]), "+f"(c[2]), "+f"(c[3])
                 : "r"(a0), "r"(a1), "r"(a2), "r"(a3), "r"(b0), "r"(b1));
}
#define LDSM4(R, A) \
    asm volatile("ldmatrix.sync.aligned.m8n8.x4.shared.b16 {%0,%1,%2,%3},[%4];" \
                 : "=r"((R)[0]), "=r"((R)[1]), "=r"((R)[2]), "=r"((R)[3]) : "r"(A))
#define CP16(dst, src) asm volatile("cp.async.ca.shared.global [%0],[%1],16;" :: "r"(dst), "l"(src) : "memory")
#define CPCOMMIT()     asm volatile("cp.async.commit_group;" ::: "memory")
#define CPWAIT0()      asm volatile("cp.async.wait_group 0;" ::: "memory")

// ---------------- prep: split weights to fp16 hi/lo ----------------
__global__ void __launch_bounds__(256) kprep(const float* __restrict__ Wd,
                                             const float* __restrict__ Wl) {
    int i = blockIdx.x * 256 + threadIdx.x;
    if (i < 128 * 512) {
        float x = Wd[i];
        __half h = __float2half_rn(x);
        g_wdh[i] = h;
        g_wdl[i] = __float2half_rn(x - __half2float(h));
    }
    if (i < 512 * 512) {
        float x = Wl[i];
        __half h = __float2half_rn(x);
        g_wlh[i] = h;
        g_wll[i] = __float2half_rn(x - __half2float(h));
    }
}

// ---------------- Kernel 1: HMMA GEMM1 + scalarizer epilogue ----------------
// CTA: 64 v-rows = 192 A-rows, N=128, K chunks of 32, double-buffered.
// 512 threads, warp grid 4(M)x4(N): warp tile 48x32. A single fp16; B = Wd hi/lo fp16.
// Row: 32 fp16 = 64B data + 16B pad -> stride 80B, conflict-free ldmatrix.
#define K1_A(b)  (1536 + (b) * 15360)
#define K1_BH(b) (32256 + (b) * 10240)
#define K1_BL(b) (52736 + (b) * 10240)
#define VST 132
#define K1_SMEM 102912

__global__ void __launch_bounds__(512) k1_kernel(const float* __restrict__ v,
                                                 const float* __restrict__ We) {
    extern __shared__ char smem[];
    const uint32_t sb = smem_u32(smem);
    const int tid = threadIdx.x, wid = tid >> 5, lane = tid & 31;
    const int wm = wid & 3, wn = wid >> 2;
    const int fr = lane >> 2, fc = lane & 3;
    const int lr = lane & 7, b8 = (lane >> 3) & 1, b16 = (lane >> 4) & 1;
    const int blk = blockIdx.x;
    const float* vbase = v + (size_t)blk * 192 * 512;

    float* sWe = (float*)smem;
    for (int i = tid; i < 384; i += 512) sWe[i] = We[i];

    // cp.async B mapping (one 16B chunk per matrix per thread)
    const int brow = tid >> 2, bseg = tid & 3;
    const uint32_t bdst = (uint32_t)(brow * 80 + bseg * 16);
    const __half* bsrc_h = g_wdh + brow * 512 + bseg * 8;
    const __half* bsrc_l = g_wdl + brow * 512 + bseg * 8;

    const uint32_t aoff = (uint32_t)((wm * 48 + lr + b8 * 8) * 80 + b16 * 16);
    const uint32_t boff = (uint32_t)((wn * 32 + lr + b8 * 8) * 80 + b16 * 16);

    float acc[3][4][4];
#pragma unroll
    for (int m = 0; m < 3; m++)
#pragma unroll
        for (int n = 0; n < 4; n++)
#pragma unroll
            for (int j = 0; j < 4; j++) acc[m][n][j] = 0.f;

    float4 va[3];
    // prologue: chunk 0
    CP16(sb + K1_BH(0) + bdst, bsrc_h);
    CP16(sb + K1_BL(0) + bdst, bsrc_l);
    CPCOMMIT();
#pragma unroll
    for (int t = 0; t < 3; t++) {
        int lin = tid + 512 * t;
        int g = lin >> 3, q = lin & 7;
        va[t] = *(const float4*)(vbase + (size_t)g * 512 + q * 4);
    }
#pragma unroll
    for (int t = 0; t < 3; t++) {
        int lin = tid + 512 * t;
        int g = lin >> 3, q = lin & 7;
        __half2 p0 = __floats2half2_rn(va[t].x, va[t].y);
        __half2 p1 = __floats2half2_rn(va[t].z, va[t].w);
        *(uint2*)(smem + K1_A(0) + g * 80 + q * 8) =
            make_uint2(*(uint32_t*)&p0, *(uint32_t*)&p1);
    }
    CPWAIT0();
    __syncthreads();

    int cur = 0;
    for (int c = 0; c < 16; c++) {
        if (c < 15) {
            const int k0n = (c + 1) * 32;
            CP16(sb + K1_BH(cur ^ 1) + bdst, bsrc_h + k0n);
            CP16(sb + K1_BL(cur ^ 1) + bdst, bsrc_l + k0n);
            CPCOMMIT();
#pragma unroll
            for (int t = 0; t < 3; t++) {
                int lin = tid + 512 * t;
                int g = lin >> 3, q = lin & 7;
                va[t] = *(const float4*)(vbase + (size_t)g * 512 + k0n + q * 4);
            }
        }
        const uint32_t A = sb + K1_A(cur);
        const uint32_t Bh = sb + K1_BH(cur), Bl = sb + K1_BL(cur);
#pragma unroll
        for (int ks = 0; ks < 2; ks++) {
            uint32_t a[3][4], bh[2][4], bl[2][4];
#pragma unroll
            for (int m = 0; m < 3; m++) LDSM4(a[m], A + aoff + m * 1280 + ks * 32);
#pragma unroll
            for (int p = 0; p < 2; p++) LDSM4(bh[p], Bh + boff + p * 1280 + ks * 32);
#pragma unroll
            for (int p = 0; p < 2; p++) LDSM4(bl[p], Bl + boff + p * 1280 + ks * 32);
#pragma unroll
            for (int m = 0; m < 3; m++)
#pragma unroll
                for (int n = 0; n < 4; n++)
                    mma_f16(acc[m][n], a[m][0], a[m][1], a[m][2], a[m][3],
                            bh[n >> 1][n & 1], bh[n >> 1][2 + (n & 1)]);
#pragma unroll
            for (int m = 0; m < 3; m++)
#pragma unroll
                for (int n = 0; n < 4; n++)
                    mma_f16(acc[m][n], a[m][0], a[m][1], a[m][2], a[m][3],
                            bl[n >> 1][n & 1], bl[n >> 1][2 + (n & 1)]);
        }
        if (c < 15) {
#pragma unroll
            for (int t = 0; t < 3; t++) {
                int lin = tid + 512 * t;
                int g = lin >> 3, q = lin & 7;
                __half2 p0 = __floats2half2_rn(va[t].x, va[t].y);
                __half2 p1 = __floats2half2_rn(va[t].z, va[t].w);
                *(uint2*)(smem + K1_A(cur ^ 1) + g * 80 + q * 8) =
                    make_uint2(*(uint32_t*)&p0, *(uint32_t*)&p1);
            }
            CPWAIT0();
        }
        __syncthreads();
        cur ^= 1;
    }

    // dump acc -> vred (union over operand buffers; safe after final sync)
    float* vred = (float*)(smem + 1536);
#pragma unroll
    for (int m = 0; m < 3; m++) {
        int row = wm * 48 + m * 16 + fr;
#pragma unroll
        for (int n = 0; n < 4; n++) {
            int col = wn * 32 + n * 8 + fc * 2;
            *(float2*)(vred + row * VST + col) = make_float2(acc[m][n][0], acc[m][n][1]);
            *(float2*)(vred + (row + 8) * VST + col) = make_float2(acc[m][n][2], acc[m][n][3]);
        }
    }
    __syncthreads();

    // ---- epilogue: norms, directions, projections -> v2 (fp16) ----
    float we[3][4];
#pragma unroll
    for (int e = 0; e < 3; e++)
#pragma unroll
        for (int c = 0; c < 4; c++) we[e][c] = sWe[e * 128 + lane + 32 * c];

    for (int t = 0; t < 4; t++) {
        int r = wid + 16 * t;
        size_t gr = (size_t)blk * 64 + r;
        float vr[3][4];
#pragma unroll
        for (int i = 0; i < 3; i++)
#pragma unroll
            for (int c = 0; c < 4; c++)
                vr[i][c] = vred[(r * 3 + i) * VST + lane + 32 * c];

        float d9[3][3];
#pragma unroll
        for (int i = 0; i < 3; i++)
#pragma unroll
            for (int e = 0; e < 3; e++) {
                float s = 0.f;
#pragma unroll
                for (int c = 0; c < 4; c++) s = fmaf(vr[i][c], we[e][c], s);
#pragma unroll
                for (int o = 16; o > 0; o >>= 1) s += __shfl_xor_sync(0xffffffffu, s, o);
                d9[i][e] = s;
            }
        float nd[3][3];
#pragma unroll
        for (int e = 0; e < 3; e++) {
            float dn = sqrtf(d9[0][e] * d9[0][e] + d9[1][e] * d9[1][e] + d9[2][e] * d9[2][e]);
            float inv = 1.f / (dn + EPS_N);
            nd[0][e] = d9[0][e] * inv;
            nd[1][e] = d9[1][e] * inv;
            nd[2][e] = d9[2][e] * inv;
        }
        __half* ov = g_v2 + gr * 512;
#pragma unroll
        for (int c = 0; c < 4; c++) {
            float n = sqrtf(vr[0][c] * vr[0][c] + vr[1][c] * vr[1][c] + vr[2][c] * vr[2][c]);
            float invn = 1.f / (n + EPS_N);
            int k = lane + 32 * c;
            ov[k] = __float2half_rn(n);
#pragma unroll
            for (int e = 0; e < 3; e++) {
                float p = (vr[0][c] * nd[0][e] + vr[1][c] * nd[1][e] + vr[2][c] * nd[2][e]) * invn;
                ov[128 + e * 128 + k] = __float2half_rn(p);
            }
        }
    }
}

// ---------------- Kernel 2: HMMA GEMM2 fused with LayerNorm+GELU ----------------
// CTA: 64 rows x full 512 cols. 512 threads, warp grid 2(M)x8(N): tile 32x64.
// A = v2 fp16 single; B = Wl hi/lo fp16.
#define K2_A(b)  ((b) * 5120)
#define K2_BH(b) (10240 + (b) * 40960)
#define K2_BL(b) (92160 + (b) * 40960)
#define K2_PSUM 174080
#define K2_PSQ 176128
#define K2_SMEM 178176

__global__ void __launch_bounds__(512) k2_kernel(const float* __restrict__ bias,
                                                 const float* __restrict__ gamma,
                                                 const float* __restrict__ beta,
                                                 float* __restrict__ out) {
    extern __shared__ char smem[];
    const uint32_t sb = smem_u32(smem);
    const int tid = threadIdx.x, wid = tid >> 5, lane = tid & 31;
    const int wm = wid & 1, wn = wid >> 1;
    const int fr = lane >> 2, fc = lane & 3;
    const int lr = lane & 7, b8 = (lane >> 3) & 1, b16 = (lane >> 4) & 1;
    const size_t row0 = (size_t)blockIdx.x * 64;

    const int arow = (tid >> 2) & 63, aseg = tid & 3;
    const __half* asrc = g_v2 + (row0 + arow) * 512 + aseg * 8;
    const uint32_t adst = (uint32_t)(arow * 80 + aseg * 16);

    const uint32_t aoff = (uint32_t)((wm * 32 + lr + b8 * 8) * 80 + b16 * 16);
    const uint32_t boff = (uint32_t)((wn * 64 + lr + b8 * 8) * 80 + b16 * 16);

    float acc[2][8][4];
#pragma unroll
    for (int m = 0; m < 2; m++)
#pragma unroll
        for (int n = 0; n < 8; n++)
#pragma unroll
            for (int j = 0; j < 4; j++) acc[m][n][j] = 0.f;

    // prologue: chunk 0
    {
        if (tid < 256) CP16(sb + K2_A(0) + adst, asrc);
#pragma unroll
        for (int i = 0; i < 8; i++) {
            int lin = tid + 512 * i;
            int mat = lin >> 11, rem = lin & 2047, r = rem >> 2, seg = rem & 3;
            const __half* src = (mat ? g_wll : g_wlh) + (size_t)r * 512 + seg * 8;
            CP16(sb + (mat ? K2_BL(0) : K2_BH(0)) + (uint32_t)(r * 80 + seg * 16), src);
        }
        CPCOMMIT();
        CPWAIT0();
        __syncthreads();
    }
    int cur = 0;
    for (int c = 0; c < 16; c++) {
        if (c < 15) {
            const int k0n = (c + 1) * 32;
            if (tid < 256) CP16(sb + K2_A(cur ^ 1) + adst, asrc + k0n);
#pragma unroll
            for (int i = 0; i < 8; i++) {
                int lin = tid + 512 * i;
                int mat = lin >> 11, rem = lin & 2047, r = rem >> 2, seg = rem & 3;
                const __half* src = (mat ? g_wll : g_wlh) + (size_t)r * 512 + k0n + seg * 8;
                CP16(sb + (mat ? K2_BL(cur ^ 1) : K2_BH(cur ^ 1)) + (uint32_t)(r * 80 + seg * 16), src);
            }
            CPCOMMIT();
        }
        const uint32_t A = sb + K2_A(cur);
        const uint32_t Bh = sb + K2_BH(cur), Bl = sb + K2_BL(cur);
#pragma unroll
        for (int ks = 0; ks < 2; ks++) {
            uint32_t a[2][4], bh[4][4], bl[4][4];
#pragma unroll
            for (int m = 0; m < 2; m++) LDSM4(a[m], A + aoff + m * 1280 + ks * 32);
#pragma unroll
            for (int p = 0; p < 4; p++) LDSM4(bh[p], Bh + boff + p * 1280 + ks * 32);
#pragma unroll
            for (int p = 0; p < 4; p++) LDSM4(bl[p], Bl + boff + p * 1280 + ks * 32);
#pragma unroll
            for (int m = 0; m < 2; m++)
#pragma unroll
                for (int n = 0; n < 8; n++)
                    mma_f16(acc[m][n], a[m][0], a[m][1], a[m][2], a[m][3],
                            bh[n >> 1][n & 1], bh[n >> 1][2 + (n & 1)]);
#pragma unroll
            for (int m = 0; m < 2; m++)
#pragma unroll
                for (int n = 0; n < 8; n++)
                    mma_f16(acc[m][n], a[m][0], a[m][1], a[m][2], a[m][3],
                            bl[n >> 1][n & 1], bl[n >> 1][2 + (n & 1)]);
        }
        if (c < 15) CPWAIT0();
        __syncthreads();
        cur ^= 1;
    }

    // ---- fused epilogue: bias + LayerNorm + exact GELU ----
#pragma unroll
    for (int n = 0; n < 8; n++) {
        int col = wn * 64 + n * 8 + fc * 2;
        float2 bb = *(const float2*)(bias + col);
#pragma unroll
        for (int m = 0; m < 2; m++) {
            acc[m][n][0] += bb.x; acc[m][n][1] += bb.y;
            acc[m][n][2] += bb.x; acc[m][n][3] += bb.y;
        }
    }
    float* psum = (float*)(smem + K2_PSUM);
    float* psq  = (float*)(smem + K2_PSQ);
#pragma unroll
    for (int m = 0; m < 2; m++)
#pragma unroll
        for (int h = 0; h < 2; h++) {
            float s = 0.f, q = 0.f;
#pragma unroll
            for (int n = 0; n < 8; n++) {
                float e0 = acc[m][n][h * 2], e1 = acc[m][n][h * 2 + 1];
                s += e0 + e1;
                q += e0 * e0 + e1 * e1;
            }
            s += __shfl_xor_sync(0xffffffffu, s, 1);
            s += __shfl_xor_sync(0xffffffffu, s, 2);
            q += __shfl_xor_sync(0xffffffffu, q, 1);
            q += __shfl_xor_sync(0xffffffffu, q, 2);
            int rr = wm * 32 + m * 16 + h * 8 + fr;
            if (fc == 0) { psum[wn * 64 + rr] = s; psq[wn * 64 + rr] = q; }
        }
    __syncthreads();

    float gg[8][2], bb2[8][2];
#pragma unroll
    for (int n = 0; n < 8; n++) {
        int col = wn * 64 + n * 8 + fc * 2;
        float2 g2 = *(const float2*)(gamma + col);
        float2 b2 = *(const float2*)(beta + col);
        gg[n][0] = g2.x; gg[n][1] = g2.y;
        bb2[n][0] = b2.x; bb2[n][1] = b2.y;
    }
    const float invs2 = 0.70710678118654752f;
#pragma unroll
    for (int m = 0; m < 2; m++)
#pragma unroll
        for (int h = 0; h < 2; h++) {
            int rr = wm * 32 + m * 16 + h * 8 + fr;
            float S = 0.f, Q = 0.f;
#pragma unroll
            for (int w = 0; w < 8; w++) { S += psum[w * 64 + rr]; Q += psq[w * 64 + rr]; }
            float mu = S * (1.f / 512.f);
            float var = Q * (1.f / 512.f) - mu * mu;
            float rstd = rsqrtf(var + LN_EPS);
            size_t orow = (row0 + rr) * 512;
#pragma unroll
            for (int n = 0; n < 8; n++) {
                int col = wn * 64 + n * 8 + fc * 2;
                float y0 = (acc[m][n][h * 2] - mu) * rstd * gg[n][0] + bb2[n][0];
                float y1 = (acc[m][n][h * 2 + 1] - mu) * rstd * gg[n][1] + bb2[n][1];
                float o0 = y0 * 0.5f * (1.f + erff(y0 * invs2));
                float o1 = y1 * 0.5f * (1.f + erff(y1 * invs2));
                *(float2*)(out + orow + col) = make_float2(o0, o1);
            }
        }
}

// ---------------- launch ----------------
extern "C" void kernel_launch(void* const* d_in, const int* in_sizes, int n_in,
                              void* d_out, int out_size) {
    const float* v     = (const float*)d_in[0];
    const float* Wd    = (const float*)d_in[1];
    const float* We    = (const float*)d_in[2];
    const float* Wl    = (const float*)d_in[3];
    const float* bl    = (const float*)d_in[4];
    const float* gamma = (const float*)d_in[5];
    const float* beta  = (const float*)d_in[6];
    float* out = (float*)d_out;

    cudaFuncSetAttribute(k1_kernel, cudaFuncAttributeMaxDynamicSharedMemorySize, K1_SMEM);
    cudaFuncSetAttribute(k2_kernel, cudaFuncAttributeMaxDynamicSharedMemorySize, K2_SMEM);

    kprep<<<1024, 256>>>(Wd, Wl);
    k1_kernel<<<NR / 64, 512, K1_SMEM>>>(v, We);
    k2_kernel<<<NR / 64, 512, K2_SMEM>>>(bl, gamma, beta, out);
}